// round 3
// baseline (speedup 1.0000x reference)
#include <cuda_runtime.h>
#include <math.h>

#define NROWS 8192      // B*T = 32*256
#define DIMC  6625
#define DIMD  96
#define BLK   256
#define NWARP (BLK / 32)

__device__ float g_rowdist[NROWS];

// Combine (val,idx) pairs keeping larger val; on tie keep SMALLER index
// (jnp.argmax first-occurrence semantics).
__device__ __forceinline__ void amax_combine(float& mv, int& mi, float ov, int oi)
{
    if (ov > mv || (ov == mv && oi < mi)) { mv = ov; mi = oi; }
}

// One block per row: argmax over predicts[n, :], then clipped squared
// distance from features[n] to centers[label].
__global__ void __launch_bounds__(BLK) center_loss_row_kernel(
    const float* __restrict__ features,   // [NROWS, 96]
    const float* __restrict__ predicts,   // [NROWS, 6625]
    const float* __restrict__ centers)    // [6625, 96]
{
    const int n    = blockIdx.x;
    const int tid  = threadIdx.x;
    const int lane = tid & 31;
    const int wid  = tid >> 5;

    __shared__ float swval[NWARP];
    __shared__ int   swidx[NWARP];
    __shared__ int   s_label;
    __shared__ float s_part[3 * NWARP];   // partial sums: ff, cc, fc per warp

    // ---- per-thread strided argmax: batch 8 loads per iteration for MLP ----
    const float* p = predicts + (size_t)n * DIMC;
    float bv = -INFINITY;
    int   bi = 0;

    int c = tid;
    // main: groups of 8 strided loads (8*256 = 2048 per group; 3 full groups
    // cover 6144, tail covers the remaining 481)
    for (; c + 7 * BLK < DIMC; c += 8 * BLK) {
        float v0 = p[c];
        float v1 = p[c + 1 * BLK];
        float v2 = p[c + 2 * BLK];
        float v3 = p[c + 3 * BLK];
        float v4 = p[c + 4 * BLK];
        float v5 = p[c + 5 * BLK];
        float v6 = p[c + 6 * BLK];
        float v7 = p[c + 7 * BLK];
        if (v0 > bv) { bv = v0; bi = c; }
        if (v1 > bv) { bv = v1; bi = c + 1 * BLK; }
        if (v2 > bv) { bv = v2; bi = c + 2 * BLK; }
        if (v3 > bv) { bv = v3; bi = c + 3 * BLK; }
        if (v4 > bv) { bv = v4; bi = c + 4 * BLK; }
        if (v5 > bv) { bv = v5; bi = c + 5 * BLK; }
        if (v6 > bv) { bv = v6; bi = c + 6 * BLK; }
        if (v7 > bv) { bv = v7; bi = c + 7 * BLK; }
    }
    for (; c < DIMC; c += BLK) {
        float v = p[c];
        if (v > bv) { bv = v; bi = c; }
    }

    // ---- warp-level argmax combine via shuffles ----
    #pragma unroll
    for (int s = 16; s > 0; s >>= 1) {
        float ov = __shfl_down_sync(0xFFFFFFFFu, bv, s);
        int   oi = __shfl_down_sync(0xFFFFFFFFu, bi, s);
        amax_combine(bv, bi, ov, oi);
    }
    if (lane == 0) { swval[wid] = bv; swidx[wid] = bi; }
    __syncthreads();

    if (tid == 0) {
        float mv = swval[0];
        int   mi = swidx[0];
        #pragma unroll
        for (int w = 1; w < NWARP; w++)
            amax_combine(mv, mi, swval[w], swidx[w]);
        s_label = mi;
    }
    __syncthreads();
    const int label = s_label;

    // ---- dot products over D=96 using first 3 warps (96 threads) ----
    float pf = 0.f, pc = 0.f, pd = 0.f;
    if (tid < DIMD) {
        float f  = features[(size_t)n * DIMD + tid];
        float cc = centers[(size_t)label * DIMD + tid];
        pf = f * f;
        pc = cc * cc;
        pd = f * cc;
    }
    if (wid < 3) {
        #pragma unroll
        for (int s = 16; s > 0; s >>= 1) {
            pf += __shfl_down_sync(0xFFFFFFFFu, pf, s);
            pc += __shfl_down_sync(0xFFFFFFFFu, pc, s);
            pd += __shfl_down_sync(0xFFFFFFFFu, pd, s);
        }
        if (lane == 0) {
            s_part[wid]             = pf;
            s_part[NWARP + wid]     = pc;
            s_part[2 * NWARP + wid] = pd;
        }
    }
    __syncthreads();

    if (tid == 0) {
        float sum_ff = s_part[0] + s_part[1] + s_part[2];
        float sum_cc = s_part[NWARP] + s_part[NWARP + 1] + s_part[NWARP + 2];
        float sum_fc = s_part[2 * NWARP] + s_part[2 * NWARP + 1] + s_part[2 * NWARP + 2];
        float dist = sum_ff + sum_cc - 2.0f * sum_fc;
        const float EPS  = 1e-07f;
        const float INFC = 100000000000.0f;
        dist = fminf(fmaxf(dist, EPS), INFC);
        g_rowdist[n] = dist;
    }
}

// Deterministic fixed-tree reduction of the 8192 per-row distances.
__global__ void __launch_bounds__(BLK) center_loss_reduce_kernel(float* out)
{
    const int tid = threadIdx.x;
    __shared__ float sred[BLK];

    float acc = 0.f;
    #pragma unroll
    for (int i = tid; i < NROWS; i += BLK)
        acc += g_rowdist[i];
    sred[tid] = acc;
    __syncthreads();

    #pragma unroll
    for (int s = BLK / 2; s > 0; s >>= 1) {
        if (tid < s) sred[tid] += sred[tid + s];
        __syncthreads();
    }
    if (tid == 0) out[0] = sred[0] / (float)NROWS;
}

extern "C" void kernel_launch(void* const* d_in, const int* in_sizes, int n_in,
                              void* d_out, int out_size)
{
    const float* features = (const float*)d_in[0];  // [32,256,96]
    const float* predicts = (const float*)d_in[1];  // [32,256,6625]
    const float* centers  = (const float*)d_in[2];  // [6625,96]
    float* out = (float*)d_out;

    center_loss_row_kernel<<<NROWS, BLK>>>(features, predicts, centers);
    center_loss_reduce_kernel<<<1, BLK>>>(out);
}